// round 13
// baseline (speedup 1.0000x reference)
#include <cuda_runtime.h>
#include <cuda_fp16.h>
#include <cstdint>

#define BATCH 4
#define SEQ   4096
#define DM    1024
#define DK    64
#define ROWS  (BATCH*SEQ)
#define NOUT  192           // Q|K|V concat

#define BM 128              // queries per CTA (flash)
#define BN 64               // kv per tile
#define NT (SEQ/BN)         // 64 tiles total
#define NZ 2                // KV splits
#define NTZ (NT/NZ)         // 32 tiles per split

// ---------------------------------------------------------------------------
// Global scratch (fp16 operands; fp32 partials for split-KV combine).
// ---------------------------------------------------------------------------
__device__ __half g_Xf [ROWS*DM];      // X in fp16 (pre-converted)
__device__ __half g_Qf [ROWS*DK];
__device__ __half g_Kf [ROWS*DK];
__device__ __half g_Vt [DK*ROWS];      // transposed [d][row]
__device__ __half g_WT [NOUT*DM];      // W^T [n][k], fp16
__device__ float  g_bias[NOUT];
__device__ float  g_Op[NZ*ROWS*DK];    // unnormalized O partials
__device__ float  g_lp[NZ*ROWS];       // row-sum partials

// ---------------------------------------------------------------------------
// Helpers (base-target PTX only)
// ---------------------------------------------------------------------------
__device__ __forceinline__ uint32_t smem_to_u32(const void* p) {
    uint32_t a;
    asm("{ .reg .u64 t; cvta.to.shared.u64 t, %1; cvt.u32.u64 %0, t; }" : "=r"(a) : "l"(p));
    return a;
}
__device__ __forceinline__ void cpasync16(uint32_t dst, const void* src) {
    asm volatile("cp.async.cg.shared.global [%0], [%1], 16;" :: "r"(dst), "l"(src));
}
#define CP_COMMIT() asm volatile("cp.async.commit_group;" ::: "memory")
#define CP_WAIT0()  asm volatile("cp.async.wait_group 0;" ::: "memory")
#define CP_WAIT1()  asm volatile("cp.async.wait_group 1;" ::: "memory")

__device__ __forceinline__ void ldsm_x4(uint32_t* r, uint32_t a) {
    asm volatile("ldmatrix.sync.aligned.m8n8.x4.shared.b16 {%0,%1,%2,%3}, [%4];"
        : "=r"(r[0]), "=r"(r[1]), "=r"(r[2]), "=r"(r[3]) : "r"(a));
}
__device__ __forceinline__ void mma_f16(float* d, const uint32_t* a,
                                        uint32_t b0, uint32_t b1) {
    asm volatile("mma.sync.aligned.m16n8k16.row.col.f32.f16.f16.f32 "
        "{%0,%1,%2,%3}, {%4,%5,%6,%7}, {%8,%9}, {%0,%1,%2,%3};"
        : "+f"(d[0]), "+f"(d[1]), "+f"(d[2]), "+f"(d[3])
        : "r"(a[0]), "r"(a[1]), "r"(a[2]), "r"(a[3]), "r"(b0), "r"(b1));
}
__device__ __forceinline__ uint32_t pack_h2(float x, float y) {
    __half2 t = __floats2half2_rn(x, y);
    return *reinterpret_cast<uint32_t*>(&t);
}
__device__ __forceinline__ uint32_t ex2_h2(uint32_t s) {
    uint32_t d;
    asm("ex2.approx.f16x2 %0, %1;" : "=r"(d) : "r"(s));
    return d;
}
__device__ __forceinline__ __half2 u2h2(uint32_t v) {
    return *reinterpret_cast<__half2*>(&v);
}

#define RSTRIDE 144u        // padded 16-bit row stride in bytes (72 elems)

// ---------------------------------------------------------------------------
// Prep (merged): blocks [0,256): W^T fp16 + bias; blocks [256, 256+8192):
// X fp32 -> fp16 (coalesced, 8 floats/thread).
// ---------------------------------------------------------------------------
#define XCONV_BLKS (ROWS * DM / 8 / 256)   // 8192

__global__ __launch_bounds__(256) void prep_all(
    const float* __restrict__ X,
    const float* __restrict__ WQ, const float* __restrict__ bQ,
    const float* __restrict__ WK, const float* __restrict__ bK,
    const float* __restrict__ WV, const float* __restrict__ bV)
{
    const int tid = threadIdx.x;
    if (blockIdx.x >= 256) {
        const int i = (blockIdx.x - 256) * 256 + tid;     // per 8 floats
        float4 a = ((const float4*)X)[2 * i];
        float4 b = ((const float4*)X)[2 * i + 1];
        uint4 v;
        v.x = pack_h2(a.x, a.y);
        v.y = pack_h2(a.z, a.w);
        v.z = pack_h2(b.x, b.y);
        v.w = pack_h2(b.z, b.w);
        ((uint4*)g_Xf)[i] = v;
        return;
    }
    __shared__ float s[NOUT][5];
    const float QSC = 0.125f * 1.4426950408889634f;
    const int k0 = blockIdx.x * 4;

    #pragma unroll
    for (int i = 0; i < 3; i++) {
        int idx = tid + i * 256;
        int k = idx / NOUT, n = idx - k * NOUT;
        float w;
        if (n < 64)       w = WQ[(size_t)(k0 + k) * DK + n] * QSC;
        else if (n < 128) w = WK[(size_t)(k0 + k) * DK + (n - 64)];
        else              w = WV[(size_t)(k0 + k) * DK + (n - 128)];
        s[n][k] = w;
    }
    __syncthreads();
    if (tid < NOUT) {
        __half hv[4];
        #pragma unroll
        for (int k = 0; k < 4; k++) hv[k] = __float2half_rn(s[tid][k]);
        *(uint2*)(g_WT + (size_t)tid * DM + k0) = *(uint2*)hv;
    }
    if (blockIdx.x == 0 && tid < NOUT) {
        float bb;
        if (tid < 64)       bb = bQ[tid] * QSC;
        else if (tid < 128) bb = bK[tid - 64];
        else                bb = bV[tid - 128];
        g_bias[tid] = bb;
    }
}

// ---------------------------------------------------------------------------
// Tensorized projection: grid (rows/256, 4), 128 threads (4 warps x 64 rows).
// Each warp: M=64 (4 A-frags) x N=48. W B-fragments reused across 4 m-tiles.
// ---------------------------------------------------------------------------
#define P_XB    0u             // X bufs: buf*36864 (256 rows)
#define P_WB    73728u         // W bufs: buf*6912 (48 rows)
#define P_BIAS  87552u         // 48 floats
#define P_TOTAL 87744u

__device__ __forceinline__ void proj_load_chunk(uint32_t sb, int tid, int r0g,
                                                int nbase, int ch)
{
    const uint32_t XB = sb + P_XB + (uint32_t)(ch & 1) * 36864u;
    const uint32_t WB = sb + P_WB + (uint32_t)(ch & 1) * 6912u;
    #pragma unroll
    for (int t = 0; t < 16; t++) {        // X: 256 rows x 8 chunks of 16B
        int idx = tid + t * 128;
        int row = idx >> 3, c = idx & 7;
        cpasync16(XB + (uint32_t)row * RSTRIDE + c * 16,
                  g_Xf + (size_t)(r0g + row) * DM + ch * 64 + c * 8);
    }
    #pragma unroll
    for (int t = 0; t < 3; t++) {         // W: 48 rows x 8 chunks
        int idx = tid + t * 128;
        int row = idx >> 3, c = idx & 7;
        cpasync16(WB + (uint32_t)row * RSTRIDE + c * 16,
                  g_WT + (size_t)(nbase + row) * DM + ch * 64 + c * 8);
    }
}

__global__ __launch_bounds__(128, 2) void proj_tc()
{
    extern __shared__ char smem[];
    const uint32_t sb = smem_to_u32(smem);
    const int tid  = threadIdx.x;
    const int wid  = tid >> 5;
    const int lane = tid & 31;
    const int gid  = lane >> 2;
    const int tq   = lane & 3;
    const int r0g  = blockIdx.x * 256;
    const int nbase = blockIdx.y * 48;

    float* biass = (float*)(smem + P_BIAS);
    if (tid < 48) biass[tid] = g_bias[nbase + tid];

    proj_load_chunk(sb, tid, r0g, nbase, 0);
    CP_COMMIT();
    CP_WAIT0();
    __syncthreads();

    float O[4][6][4];
    #pragma unroll
    for (int m = 0; m < 4; m++)
        #pragma unroll
        for (int n = 0; n < 6; n++)
            #pragma unroll
            for (int c = 0; c < 4; c++) O[m][n][c] = 0.f;

    uint32_t aoff[4];
    #pragma unroll
    for (int m = 0; m < 4; m++)
        aoff[m] = (uint32_t)(wid * 64 + m * 16 + (lane & 15)) * RSTRIDE
                + (uint32_t)(lane >> 4) * 16;
    const uint32_t boff = (uint32_t)(((lane >> 4) & 1) * 8 + (lane & 7)) * RSTRIDE
                        + (uint32_t)((lane >> 3) & 1) * 16;

    for (int ch = 0; ch < 16; ch++) {
        const uint32_t XB = sb + P_XB + (uint32_t)(ch & 1) * 36864u;
        const uint32_t WB = sb + P_WB + (uint32_t)(ch & 1) * 6912u;
        const int nxt = ch + 1;

        if (nxt < 16) {
            proj_load_chunk(sb, tid, r0g, nbase, nxt);
            CP_COMMIT();
        }

        #pragma unroll
        for (int kc = 0; kc < 4; kc++) {
            uint32_t xa[4][4];
            #pragma unroll
            for (int m = 0; m < 4; m++)
                ldsm_x4(xa[m], XB + aoff[m] + kc * 32);
            #pragma unroll
            for (int p = 0; p < 3; p++) {
                uint32_t wh[4];
                ldsm_x4(wh, WB + boff + (uint32_t)p * (16 * RSTRIDE) + kc * 32);
                #pragma unroll
                for (int m = 0; m < 4; m++) {
                    mma_f16(O[m][2*p],   xa[m], wh[0], wh[1]);
                    mma_f16(O[m][2*p+1], xa[m], wh[2], wh[3]);
                }
            }
        }

        if (nxt < 16) CP_WAIT0();
        __syncthreads();
    }

    // ---- epilogue: +bias, emit fp16 flash operands
    #pragma unroll
    for (int m = 0; m < 4; m++) {
        const int rr0 = r0g + wid * 64 + m * 16 + gid;
        const int rr1 = rr0 + 8;
        #pragma unroll
        for (int nt = 0; nt < 6; nt++) {
            const int cl = nt * 8 + 2 * tq;
            const int cg = nbase + cl;
            const float b0 = biass[cl], b1 = biass[cl + 1];
            float v00 = O[m][nt][0] + b0, v01 = O[m][nt][1] + b1;
            float v10 = O[m][nt][2] + b0, v11 = O[m][nt][3] + b1;
            if (cg < 64) {
                *(__half2*)(g_Qf + (size_t)rr0 * DK + cg) = __floats2half2_rn(v00, v01);
                *(__half2*)(g_Qf + (size_t)rr1 * DK + cg) = __floats2half2_rn(v10, v11);
            } else if (cg < 128) {
                const int ck = cg - 64;
                *(__half2*)(g_Kf + (size_t)rr0 * DK + ck) = __floats2half2_rn(v00, v01);
                *(__half2*)(g_Kf + (size_t)rr1 * DK + ck) = __floats2half2_rn(v10, v11);
            } else {
                const int d0 = cg - 128, d1 = d0 + 1;
                g_Vt[(size_t)d0 * ROWS + rr0] = __float2half_rn(v00);
                g_Vt[(size_t)d1 * ROWS + rr0] = __float2half_rn(v01);
                g_Vt[(size_t)d0 * ROWS + rr1] = __float2half_rn(v10);
                g_Vt[(size_t)d1 * ROWS + rr1] = __float2half_rn(v11);
            }
        }
    }
}

// ---------------------------------------------------------------------------
// Flash attention (verified round-11 body): 128 threads (4 warps x 32 rows),
// BM=128, split-KV NZ=2, fp32 S, fp16x2 exp.
// ---------------------------------------------------------------------------
#define SM_QF   0u
#define SM_BUF0 18432u
#define SM_BUFSZ 18432u      // K +0 (9216), V +9216
#define SM_TOTAL (SM_BUF0 + 3*SM_BUFSZ)

__device__ __forceinline__ void load_kv(uint32_t dst, int tid, size_t bSE, int j0)
{
    #pragma unroll
    for (int t = 0; t < 4; t++) {
        int i = tid + t * 128;            // K: 64 rows x 8 chunks
        int row = i >> 3, c = i & 7;
        cpasync16(dst + row * RSTRIDE + c * 16,
                  g_Kf + (bSE + j0 + row) * DK + c * 8);
    }
    #pragma unroll
    for (int t = 0; t < 4; t++) {
        int i = tid + t * 128;            // V: [d][key]
        int d = i >> 3, c = i & 7;
        cpasync16(dst + 9216u + d * RSTRIDE + c * 16,
                  g_Vt + (size_t)d * ROWS + bSE + j0 + c * 8);
    }
}

__global__ __launch_bounds__(128, 2) void flash_mma()
{
    extern __shared__ char smem[];
    const uint32_t sb = smem_to_u32(smem);
    const int tid  = threadIdx.x;
    const int wid  = tid >> 5;
    const int lane = tid & 31;
    const int gid  = lane >> 2;
    const int tq   = lane & 3;

    const int b  = blockIdx.y;
    const int q0 = blockIdx.x * BM;
    const int z  = blockIdx.z;
    const int k0base = z * NTZ * BN;
    const size_t bSE = (size_t)b * SEQ;

    #pragma unroll
    for (int t = 0; t < 8; t++) {
        int idx = tid + t * 128;          // 128 rows x 8 chunks
        int row = idx >> 3, c = idx & 7;
        cpasync16(sb + SM_QF + row * RSTRIDE + c * 16,
                  g_Qf + (bSE + q0 + row) * DK + c * 8);
    }
    load_kv(sb + SM_BUF0, tid, bSE, k0base);
    CP_COMMIT();
    load_kv(sb + SM_BUF0 + SM_BUFSZ, tid, bSE, k0base + BN);
    CP_COMMIT();
    CP_WAIT1();
    __syncthreads();

    uint32_t qf[2][4][4];
    {
        const uint32_t a0 = (uint32_t)(wid * 32 + (lane & 15)) * RSTRIDE + (uint32_t)(lane >> 4) * 16;
        #pragma unroll
        for (int kc = 0; kc < 4; kc++) {
            ldsm_x4(qf[0][kc], sb + SM_QF + a0 + kc * 32);
            ldsm_x4(qf[1][kc], sb + SM_QF + a0 + 16 * RSTRIDE + kc * 32);
        }
    }

    float O[2][8][4];
    #pragma unroll
    for (int m = 0; m < 2; m++)
        #pragma unroll
        for (int i = 0; i < 8; i++)
            #pragma unroll
            for (int c = 0; c < 4; c++) O[m][i][c] = 0.f;
    float lsum[2][2] = {{0.f, 0.f}, {0.f, 0.f}};

    const uint32_t boff = (uint32_t)(((lane >> 4) & 1) * 8 + (lane & 7)) * RSTRIDE
                        + (uint32_t)((lane >> 3) & 1) * 16;

    const uint32_t bufs[3] = {sb + SM_BUF0, sb + SM_BUF0 + SM_BUFSZ, sb + SM_BUF0 + 2*SM_BUFSZ};

    for (int j = 0; j < NTZ; j++) {
        const uint32_t buf = bufs[j % 3];

        float S[2][8][4];
        #pragma unroll
        for (int m = 0; m < 2; m++)
            #pragma unroll
            for (int i = 0; i < 8; i++)
                #pragma unroll
                for (int c = 0; c < 4; c++) S[m][i][c] = 0.f;

        #pragma unroll
        for (int kc = 0; kc < 4; kc++) {
            #pragma unroll
            for (int nph = 0; nph < 2; nph++) {
                uint32_t r0[4], r1[4];
                ldsm_x4(r0, buf + boff + (uint32_t)(2*nph)   * (16 * RSTRIDE) + kc * 32);
                ldsm_x4(r1, buf + boff + (uint32_t)(2*nph+1) * (16 * RSTRIDE) + kc * 32);
                #pragma unroll
                for (int m = 0; m < 2; m++) {
                    mma_f16(S[m][4*nph],   qf[m][kc], r0[0], r0[1]);
                    mma_f16(S[m][4*nph+1], qf[m][kc], r0[2], r0[3]);
                    mma_f16(S[m][4*nph+2], qf[m][kc], r1[0], r1[1]);
                    mma_f16(S[m][4*nph+3], qf[m][kc], r1[2], r1[3]);
                }
            }
        }

        uint32_t Pf[2][4][4];
        #pragma unroll
        for (int m = 0; m < 2; m++) {
            __half2 a0 = __floats2half2_rn(0.f, 0.f);
            __half2 a1 = a0;
            #pragma unroll
            for (int kc2 = 0; kc2 < 4; kc2++) {
                const int nt0 = 2 * kc2, nt1 = nt0 + 1;
                Pf[m][kc2][0] = ex2_h2(pack_h2(S[m][nt0][0], S[m][nt0][1]));
                Pf[m][kc2][1] = ex2_h2(pack_h2(S[m][nt0][2], S[m][nt0][3]));
                Pf[m][kc2][2] = ex2_h2(pack_h2(S[m][nt1][0], S[m][nt1][1]));
                Pf[m][kc2][3] = ex2_h2(pack_h2(S[m][nt1][2], S[m][nt1][3]));
                a0 = __hadd2(a0, __hadd2(u2h2(Pf[m][kc2][0]), u2h2(Pf[m][kc2][2])));
                a1 = __hadd2(a1, __hadd2(u2h2(Pf[m][kc2][1]), u2h2(Pf[m][kc2][3])));
            }
            lsum[m][0] += __low2float(a0) + __high2float(a0);
            lsum[m][1] += __low2float(a1) + __high2float(a1);
        }

        #pragma unroll
        for (int kc2 = 0; kc2 < 4; kc2++) {
            #pragma unroll
            for (int nph = 0; nph < 2; nph++) {
                uint32_t r0[4], r1[4];
                ldsm_x4(r0, buf + 9216u + boff + (uint32_t)(2*nph)   * (16 * RSTRIDE) + kc2 * 32);
                ldsm_x4(r1, buf + 9216u + boff + (uint32_t)(2*nph+1) * (16 * RSTRIDE) + kc2 * 32);
                #pragma unroll
                for (int m = 0; m < 2; m++) {
                    mma_f16(O[m][4*nph],   Pf[m][kc2], r0[0], r0[1]);
                    mma_f16(O[m][4*nph+1], Pf[m][kc2], r0[2], r0[3]);
                    mma_f16(O[m][4*nph+2], Pf[m][kc2], r1[0], r1[1]);
                    mma_f16(O[m][4*nph+3], Pf[m][kc2], r1[2], r1[3]);
                }
            }
        }

        if (j + 2 < NTZ) {
            load_kv(bufs[(j + 2) % 3], tid, bSE, k0base + (j + 2) * BN);
            CP_COMMIT();
            CP_WAIT1();
        } else {
            CP_WAIT0();
        }
        __syncthreads();
    }

    #pragma unroll
    for (int m = 0; m < 2; m++) {
        lsum[m][0] += __shfl_xor_sync(0xffffffffu, lsum[m][0], 1);
        lsum[m][0] += __shfl_xor_sync(0xffffffffu, lsum[m][0], 2);
        lsum[m][1] += __shfl_xor_sync(0xffffffffu, lsum[m][1], 1);
        lsum[m][1] += __shfl_xor_sync(0xffffffffu, lsum[m][1], 2);

        const int row0 = q0 + wid * 32 + m * 16 + gid;
        float* o0 = g_Op + ((size_t)z * ROWS + bSE + row0) * DK;
        float* o1 = o0 + 8 * DK;
        if (tq == 0) {
            g_lp[(size_t)z * ROWS + bSE + row0]     = lsum[m][0];
            g_lp[(size_t)z * ROWS + bSE + row0 + 8] = lsum[m][1];
        }
        #pragma unroll
        for (int nt = 0; nt < 8; nt++) {
            const int col = nt * 8 + 2 * tq;
            *(float2*)(o0 + col) = make_float2(O[m][nt][0], O[m][nt][1]);
            *(float2*)(o1 + col) = make_float2(O[m][nt][2], O[m][nt][3]);
        }
    }
}

// ---------------------------------------------------------------------------
// Combine: out = (O0 + O1) / (l0 + l1)  (round-11 form)
// ---------------------------------------------------------------------------
__global__ __launch_bounds__(256) void combine(float* __restrict__ out)
{
    const int idx = blockIdx.x * 256 + threadIdx.x;   // float4 index, 16/row
    const int row = idx >> 4;
    const float inv = 1.f / (g_lp[row] + g_lp[ROWS + row]);
    const float4 a = ((const float4*)g_Op)[idx];
    const float4 b = ((const float4*)g_Op)[idx + (ROWS * DK / 4)];
    float4 r;
    r.x = (a.x + b.x) * inv;
    r.y = (a.y + b.y) * inv;
    r.z = (a.z + b.z) * inv;
    r.w = (a.w + b.w) * inv;
    ((float4*)out)[idx] = r;
}

// ---------------------------------------------------------------------------
extern "C" void kernel_launch(void* const* d_in, const int* in_sizes, int n_in,
                              void* d_out, int out_size)
{
    const float* X  = (const float*)d_in[0];
    // d_in[1] cultural_embedding, d_in[8..10] WC,bC,lam: softmax-invariant -> unused
    const float* WQ = (const float*)d_in[2];
    const float* bQ = (const float*)d_in[3];
    const float* WK = (const float*)d_in[4];
    const float* bK = (const float*)d_in[5];
    const float* WV = (const float*)d_in[6];
    const float* bV = (const float*)d_in[7];
    float* out = (float*)d_out;

    cudaFuncSetAttribute(proj_tc,   cudaFuncAttributeMaxDynamicSharedMemorySize, P_TOTAL);
    cudaFuncSetAttribute(flash_mma, cudaFuncAttributeMaxDynamicSharedMemorySize, SM_TOTAL);

    prep_all<<<256 + XCONV_BLKS, 256>>>(X, WQ, bQ, WK, bK, WV, bV);
    proj_tc<<<dim3(ROWS / 256, 4), 128, P_TOTAL>>>();
    flash_mma<<<dim3(SEQ / BM, BATCH, NZ), 128, SM_TOTAL>>>();
    combine<<<ROWS * DK / 4 / 256, 256>>>(out);
}

// round 14
// speedup vs baseline: 1.3250x; 1.3250x over previous
#include <cuda_runtime.h>
#include <cuda_fp16.h>
#include <cstdint>

#define BATCH 4
#define SEQ   4096
#define DM    1024
#define DK    64
#define ROWS  (BATCH*SEQ)
#define NOUT  192           // Q|K|V concat

#define BM 128              // queries per CTA (flash)
#define BN 64               // kv per tile
#define NT (SEQ/BN)         // 64 tiles total
#define NZ 2                // KV splits
#define NTZ (NT/NZ)         // 32 tiles per split

// ---------------------------------------------------------------------------
// Global scratch (fp16 operands; fp32 partials for split-KV combine).
// ---------------------------------------------------------------------------
__device__ __half g_Xf [ROWS*DM];      // X in fp16 (pre-converted)
__device__ __half g_Qf [ROWS*DK];
__device__ __half g_Kf [ROWS*DK];
__device__ __half g_Vt [DK*ROWS];      // transposed [d][row]
__device__ __half g_WT [NOUT*DM];      // W^T [n][k], fp16
__device__ float  g_bias[NOUT];
__device__ float  g_Op[NZ*ROWS*DK];    // unnormalized O partials
__device__ float  g_lp[NZ*ROWS];       // row-sum partials

// ---------------------------------------------------------------------------
// Helpers (base-target PTX only)
// ---------------------------------------------------------------------------
__device__ __forceinline__ uint32_t smem_to_u32(const void* p) {
    uint32_t a;
    asm("{ .reg .u64 t; cvta.to.shared.u64 t, %1; cvt.u32.u64 %0, t; }" : "=r"(a) : "l"(p));
    return a;
}
__device__ __forceinline__ void cpasync16(uint32_t dst, const void* src) {
    asm volatile("cp.async.cg.shared.global [%0], [%1], 16;" :: "r"(dst), "l"(src));
}
#define CP_COMMIT() asm volatile("cp.async.commit_group;" ::: "memory")
#define CP_WAIT0()  asm volatile("cp.async.wait_group 0;" ::: "memory")
#define CP_WAIT1()  asm volatile("cp.async.wait_group 1;" ::: "memory")

__device__ __forceinline__ void ldsm_x4(uint32_t* r, uint32_t a) {
    asm volatile("ldmatrix.sync.aligned.m8n8.x4.shared.b16 {%0,%1,%2,%3}, [%4];"
        : "=r"(r[0]), "=r"(r[1]), "=r"(r[2]), "=r"(r[3]) : "r"(a));
}
__device__ __forceinline__ void mma_f16(float* d, const uint32_t* a,
                                        uint32_t b0, uint32_t b1) {
    asm volatile("mma.sync.aligned.m16n8k16.row.col.f32.f16.f16.f32 "
        "{%0,%1,%2,%3}, {%4,%5,%6,%7}, {%8,%9}, {%0,%1,%2,%3};"
        : "+f"(d[0]), "+f"(d[1]), "+f"(d[2]), "+f"(d[3])
        : "r"(a[0]), "r"(a[1]), "r"(a[2]), "r"(a[3]), "r"(b0), "r"(b1));
}
__device__ __forceinline__ void mma_f16d16(uint32_t* d, const uint32_t* a,
                                           uint32_t b0, uint32_t b1) {
    asm volatile("mma.sync.aligned.m16n8k16.row.col.f16.f16.f16.f16 "
        "{%0,%1}, {%2,%3,%4,%5}, {%6,%7}, {%0,%1};"
        : "+r"(d[0]), "+r"(d[1])
        : "r"(a[0]), "r"(a[1]), "r"(a[2]), "r"(a[3]), "r"(b0), "r"(b1));
}
__device__ __forceinline__ uint32_t pack_h2(float x, float y) {
    __half2 t = __floats2half2_rn(x, y);
    return *reinterpret_cast<uint32_t*>(&t);
}
__device__ __forceinline__ uint32_t ex2_h2(uint32_t s) {
    uint32_t d;
    asm("ex2.approx.f16x2 %0, %1;" : "=r"(d) : "r"(s));
    return d;
}
__device__ __forceinline__ __half2 u2h2(uint32_t v) {
    return *reinterpret_cast<__half2*>(&v);
}

#define RSTRIDE 144u        // padded 16-bit row stride in bytes (72 elems)

// ---------------------------------------------------------------------------
// Prep (merged): blocks [0,256): W^T fp16 + bias; blocks [256, 256+8192):
// X fp32 -> fp16 (coalesced, 8 floats/thread).
// ---------------------------------------------------------------------------
#define XCONV_BLKS (ROWS * DM / 8 / 256)   // 8192

__global__ __launch_bounds__(256) void prep_all(
    const float* __restrict__ X,
    const float* __restrict__ WQ, const float* __restrict__ bQ,
    const float* __restrict__ WK, const float* __restrict__ bK,
    const float* __restrict__ WV, const float* __restrict__ bV)
{
    const int tid = threadIdx.x;
    if (blockIdx.x >= 256) {
        const int i = (blockIdx.x - 256) * 256 + tid;     // per 8 floats
        float4 a = ((const float4*)X)[2 * i];
        float4 b = ((const float4*)X)[2 * i + 1];
        uint4 v;
        v.x = pack_h2(a.x, a.y);
        v.y = pack_h2(a.z, a.w);
        v.z = pack_h2(b.x, b.y);
        v.w = pack_h2(b.z, b.w);
        ((uint4*)g_Xf)[i] = v;
        return;
    }
    __shared__ float s[NOUT][5];
    const float QSC = 0.125f * 1.4426950408889634f;
    const int k0 = blockIdx.x * 4;

    #pragma unroll
    for (int i = 0; i < 3; i++) {
        int idx = tid + i * 256;
        int k = idx / NOUT, n = idx - k * NOUT;
        float w;
        if (n < 64)       w = WQ[(size_t)(k0 + k) * DK + n] * QSC;
        else if (n < 128) w = WK[(size_t)(k0 + k) * DK + (n - 64)];
        else              w = WV[(size_t)(k0 + k) * DK + (n - 128)];
        s[n][k] = w;
    }
    __syncthreads();
    if (tid < NOUT) {
        __half hv[4];
        #pragma unroll
        for (int k = 0; k < 4; k++) hv[k] = __float2half_rn(s[tid][k]);
        *(uint2*)(g_WT + (size_t)tid * DM + k0) = *(uint2*)hv;
    }
    if (blockIdx.x == 0 && tid < NOUT) {
        float bb;
        if (tid < 64)       bb = bQ[tid] * QSC;
        else if (tid < 128) bb = bK[tid - 64];
        else                bb = bV[tid - 128];
        g_bias[tid] = bb;
    }
}

// ---------------------------------------------------------------------------
// Tensorized projection: grid (rows/256, 2), 128 threads (4 warps x 64 rows).
// M=64 per warp (4 A-frags), N=96. X traffic identical to round-11 (ny=2).
// ---------------------------------------------------------------------------
#define P_XB    0u             // X bufs: buf*36864 (256 rows)
#define P_WB    73728u         // W bufs: buf*13824 (96 rows)
#define P_BIAS  101376u        // 96 floats
#define P_TOTAL 101760u

__device__ __forceinline__ void proj_load_chunk(uint32_t sb, int tid, int r0g,
                                                int nbase, int ch)
{
    const uint32_t XB = sb + P_XB + (uint32_t)(ch & 1) * 36864u;
    const uint32_t WB = sb + P_WB + (uint32_t)(ch & 1) * 13824u;
    #pragma unroll
    for (int t = 0; t < 16; t++) {        // X: 256 rows x 8 chunks of 16B
        int idx = tid + t * 128;
        int row = idx >> 3, c = idx & 7;
        cpasync16(XB + (uint32_t)row * RSTRIDE + c * 16,
                  g_Xf + (size_t)(r0g + row) * DM + ch * 64 + c * 8);
    }
    #pragma unroll
    for (int t = 0; t < 6; t++) {         // W: 96 rows x 8 chunks
        int idx = tid + t * 128;
        int row = idx >> 3, c = idx & 7;
        cpasync16(WB + (uint32_t)row * RSTRIDE + c * 16,
                  g_WT + (size_t)(nbase + row) * DM + ch * 64 + c * 8);
    }
}

__global__ __launch_bounds__(128, 2) void proj_tc()
{
    extern __shared__ char smem[];
    const uint32_t sb = smem_to_u32(smem);
    const int tid  = threadIdx.x;
    const int wid  = tid >> 5;
    const int lane = tid & 31;
    const int gid  = lane >> 2;
    const int tq   = lane & 3;
    const int r0g  = blockIdx.x * 256;
    const int nbase = blockIdx.y * 96;

    float* biass = (float*)(smem + P_BIAS);
    if (tid < 96) biass[tid] = g_bias[nbase + tid];

    proj_load_chunk(sb, tid, r0g, nbase, 0);
    CP_COMMIT();
    CP_WAIT0();
    __syncthreads();

    float O[4][12][4];
    #pragma unroll
    for (int m = 0; m < 4; m++)
        #pragma unroll
        for (int n = 0; n < 12; n++)
            #pragma unroll
            for (int c = 0; c < 4; c++) O[m][n][c] = 0.f;

    uint32_t aoff[4];
    #pragma unroll
    for (int m = 0; m < 4; m++)
        aoff[m] = (uint32_t)(wid * 64 + m * 16 + (lane & 15)) * RSTRIDE
                + (uint32_t)(lane >> 4) * 16;
    const uint32_t boff = (uint32_t)(((lane >> 4) & 1) * 8 + (lane & 7)) * RSTRIDE
                        + (uint32_t)((lane >> 3) & 1) * 16;

    for (int ch = 0; ch < 16; ch++) {
        const uint32_t XB = sb + P_XB + (uint32_t)(ch & 1) * 36864u;
        const uint32_t WB = sb + P_WB + (uint32_t)(ch & 1) * 13824u;
        const int nxt = ch + 1;

        if (nxt < 16) {
            proj_load_chunk(sb, tid, r0g, nbase, nxt);
            CP_COMMIT();
        }

        #pragma unroll
        for (int kc = 0; kc < 4; kc++) {
            uint32_t xa[4][4];
            #pragma unroll
            for (int m = 0; m < 4; m++)
                ldsm_x4(xa[m], XB + aoff[m] + kc * 32);
            #pragma unroll
            for (int p = 0; p < 6; p++) {
                uint32_t wh[4];
                ldsm_x4(wh, WB + boff + (uint32_t)p * (16 * RSTRIDE) + kc * 32);
                #pragma unroll
                for (int m = 0; m < 4; m++) {
                    mma_f16(O[m][2*p],   xa[m], wh[0], wh[1]);
                    mma_f16(O[m][2*p+1], xa[m], wh[2], wh[3]);
                }
            }
        }

        if (nxt < 16) CP_WAIT0();
        __syncthreads();
    }

    // ---- epilogue: +bias, emit fp16 flash operands
    #pragma unroll
    for (int m = 0; m < 4; m++) {
        const int rr0 = r0g + wid * 64 + m * 16 + gid;
        const int rr1 = rr0 + 8;
        #pragma unroll
        for (int nt = 0; nt < 12; nt++) {
            const int cl = nt * 8 + 2 * tq;
            const int cg = nbase + cl;
            const float b0 = biass[cl], b1 = biass[cl + 1];
            float v00 = O[m][nt][0] + b0, v01 = O[m][nt][1] + b1;
            float v10 = O[m][nt][2] + b0, v11 = O[m][nt][3] + b1;
            if (cg < 64) {
                *(__half2*)(g_Qf + (size_t)rr0 * DK + cg) = __floats2half2_rn(v00, v01);
                *(__half2*)(g_Qf + (size_t)rr1 * DK + cg) = __floats2half2_rn(v10, v11);
            } else if (cg < 128) {
                const int ck = cg - 64;
                *(__half2*)(g_Kf + (size_t)rr0 * DK + ck) = __floats2half2_rn(v00, v01);
                *(__half2*)(g_Kf + (size_t)rr1 * DK + ck) = __floats2half2_rn(v10, v11);
            } else {
                const int d0 = cg - 128, d1 = d0 + 1;
                g_Vt[(size_t)d0 * ROWS + rr0] = __float2half_rn(v00);
                g_Vt[(size_t)d1 * ROWS + rr0] = __float2half_rn(v01);
                g_Vt[(size_t)d0 * ROWS + rr1] = __float2half_rn(v10);
                g_Vt[(size_t)d1 * ROWS + rr1] = __float2half_rn(v11);
            }
        }
    }
}

// ---------------------------------------------------------------------------
// Flash attention: round-11 structure (m=2, BM=128, NZ=2) with fp16-S
// accumulation (r12-validated numerics): S fp16-D, in-place ex2, D-frag ==
// PV A-frag.
// ---------------------------------------------------------------------------
#define SM_QF   0u
#define SM_BUF0 18432u
#define SM_BUFSZ 18432u      // K +0 (9216), V +9216
#define SM_TOTAL (SM_BUF0 + 3*SM_BUFSZ)

__device__ __forceinline__ void load_kv(uint32_t dst, int tid, size_t bSE, int j0)
{
    #pragma unroll
    for (int t = 0; t < 4; t++) {
        int i = tid + t * 128;            // K: 64 rows x 8 chunks
        int row = i >> 3, c = i & 7;
        cpasync16(dst + row * RSTRIDE + c * 16,
                  g_Kf + (bSE + j0 + row) * DK + c * 8);
    }
    #pragma unroll
    for (int t = 0; t < 4; t++) {
        int i = tid + t * 128;            // V: [d][key]
        int d = i >> 3, c = i & 7;
        cpasync16(dst + 9216u + d * RSTRIDE + c * 16,
                  g_Vt + (size_t)d * ROWS + bSE + j0 + c * 8);
    }
}

__global__ __launch_bounds__(128, 2) void flash_mma()
{
    extern __shared__ char smem[];
    const uint32_t sb = smem_to_u32(smem);
    const int tid  = threadIdx.x;
    const int wid  = tid >> 5;
    const int lane = tid & 31;
    const int gid  = lane >> 2;
    const int tq   = lane & 3;

    const int b  = blockIdx.y;
    const int q0 = blockIdx.x * BM;
    const int z  = blockIdx.z;
    const int k0base = z * NTZ * BN;
    const size_t bSE = (size_t)b * SEQ;

    #pragma unroll
    for (int t = 0; t < 8; t++) {
        int idx = tid + t * 128;          // 128 rows x 8 chunks
        int row = idx >> 3, c = idx & 7;
        cpasync16(sb + SM_QF + row * RSTRIDE + c * 16,
                  g_Qf + (bSE + q0 + row) * DK + c * 8);
    }
    load_kv(sb + SM_BUF0, tid, bSE, k0base);
    CP_COMMIT();
    load_kv(sb + SM_BUF0 + SM_BUFSZ, tid, bSE, k0base + BN);
    CP_COMMIT();
    CP_WAIT1();
    __syncthreads();

    uint32_t qf[2][4][4];
    {
        const uint32_t a0 = (uint32_t)(wid * 32 + (lane & 15)) * RSTRIDE + (uint32_t)(lane >> 4) * 16;
        #pragma unroll
        for (int kc = 0; kc < 4; kc++) {
            ldsm_x4(qf[0][kc], sb + SM_QF + a0 + kc * 32);
            ldsm_x4(qf[1][kc], sb + SM_QF + a0 + 16 * RSTRIDE + kc * 32);
        }
    }

    float O[2][8][4];
    #pragma unroll
    for (int m = 0; m < 2; m++)
        #pragma unroll
        for (int i = 0; i < 8; i++)
            #pragma unroll
            for (int c = 0; c < 4; c++) O[m][i][c] = 0.f;
    float lsum[2][2] = {{0.f, 0.f}, {0.f, 0.f}};

    const uint32_t boff = (uint32_t)(((lane >> 4) & 1) * 8 + (lane & 7)) * RSTRIDE
                        + (uint32_t)((lane >> 3) & 1) * 16;

    const uint32_t bufs[3] = {sb + SM_BUF0, sb + SM_BUF0 + SM_BUFSZ, sb + SM_BUF0 + 2*SM_BUFSZ};

    for (int j = 0; j < NTZ; j++) {
        const uint32_t buf = bufs[j % 3];

        // ---- S = Q K^T, fp16 accumulators (S[m][nt][2]; nt = n8 tile)
        uint32_t S[2][8][2];
        #pragma unroll
        for (int m = 0; m < 2; m++)
            #pragma unroll
            for (int nt = 0; nt < 8; nt++) { S[m][nt][0] = 0u; S[m][nt][1] = 0u; }

        #pragma unroll
        for (int kc = 0; kc < 4; kc++) {
            #pragma unroll
            for (int nph = 0; nph < 2; nph++) {
                uint32_t r0[4], r1[4];
                ldsm_x4(r0, buf + boff + (uint32_t)(2*nph)   * (16 * RSTRIDE) + kc * 32);
                ldsm_x4(r1, buf + boff + (uint32_t)(2*nph+1) * (16 * RSTRIDE) + kc * 32);
                #pragma unroll
                for (int m = 0; m < 2; m++) {
                    mma_f16d16(S[m][4*nph],   qf[m][kc], r0[0], r0[1]);
                    mma_f16d16(S[m][4*nph+1], qf[m][kc], r0[2], r0[3]);
                    mma_f16d16(S[m][4*nph+2], qf[m][kc], r1[0], r1[1]);
                    mma_f16d16(S[m][4*nph+3], qf[m][kc], r1[2], r1[3]);
                }
            }
        }

        // ---- softmax in place: P = ex2(S); fp16 D-frag == PV A-frag layout
        #pragma unroll
        for (int m = 0; m < 2; m++) {
            __half2 a0 = __floats2half2_rn(0.f, 0.f);
            __half2 a1 = a0;
            #pragma unroll
            for (int nt = 0; nt < 8; nt++) {
                S[m][nt][0] = ex2_h2(S[m][nt][0]);
                S[m][nt][1] = ex2_h2(S[m][nt][1]);
                a0 = __hadd2(a0, u2h2(S[m][nt][0]));
                a1 = __hadd2(a1, u2h2(S[m][nt][1]));
            }
            lsum[m][0] += __low2float(a0) + __high2float(a0);
            lsum[m][1] += __low2float(a1) + __high2float(a1);
        }

        // ---- O += P Vt; A-frag = &S[m][2*kc2][0] (4 consecutive regs)
        #pragma unroll
        for (int kc2 = 0; kc2 < 4; kc2++) {
            #pragma unroll
            for (int nph = 0; nph < 2; nph++) {
                uint32_t r0[4], r1[4];
                ldsm_x4(r0, buf + 9216u + boff + (uint32_t)(2*nph)   * (16 * RSTRIDE) + kc2 * 32);
                ldsm_x4(r1, buf + 9216u + boff + (uint32_t)(2*nph+1) * (16 * RSTRIDE) + kc2 * 32);
                #pragma unroll
                for (int m = 0; m < 2; m++) {
                    mma_f16(O[m][4*nph],   &S[m][2*kc2][0], r0[0], r0[1]);
                    mma_f16(O[m][4*nph+1], &S[m][2*kc2][0], r0[2], r0[3]);
                    mma_f16(O[m][4*nph+2], &S[m][2*kc2][0], r1[0], r1[1]);
                    mma_f16(O[m][4*nph+3], &S[m][2*kc2][0], r1[2], r1[3]);
                }
            }
        }

        if (j + 2 < NTZ) {
            load_kv(bufs[(j + 2) % 3], tid, bSE, k0base + (j + 2) * BN);
            CP_COMMIT();
            CP_WAIT1();
        } else {
            CP_WAIT0();
        }
        __syncthreads();
    }

    #pragma unroll
    for (int m = 0; m < 2; m++) {
        lsum[m][0] += __shfl_xor_sync(0xffffffffu, lsum[m][0], 1);
        lsum[m][0] += __shfl_xor_sync(0xffffffffu, lsum[m][0], 2);
        lsum[m][1] += __shfl_xor_sync(0xffffffffu, lsum[m][1], 1);
        lsum[m][1] += __shfl_xor_sync(0xffffffffu, lsum[m][1], 2);

        const int row0 = q0 + wid * 32 + m * 16 + gid;
        float* o0 = g_Op + ((size_t)z * ROWS + bSE + row0) * DK;
        float* o1 = o0 + 8 * DK;
        if (tq == 0) {
            g_lp[(size_t)z * ROWS + bSE + row0]     = lsum[m][0];
            g_lp[(size_t)z * ROWS + bSE + row0 + 8] = lsum[m][1];
        }
        #pragma unroll
        for (int nt = 0; nt < 8; nt++) {
            const int col = nt * 8 + 2 * tq;
            *(float2*)(o0 + col) = make_float2(O[m][nt][0], O[m][nt][1]);
            *(float2*)(o1 + col) = make_float2(O[m][nt][2], O[m][nt][3]);
        }
    }
}

// ---------------------------------------------------------------------------
// Combine: out = (O0 + O1) / (l0 + l1)
// ---------------------------------------------------------------------------
__global__ __launch_bounds__(256) void combine(float* __restrict__ out)
{
    const int idx = blockIdx.x * 256 + threadIdx.x;   // float4 index, 16/row
    const int row = idx >> 4;
    const float inv = 1.f / (g_lp[row] + g_lp[ROWS + row]);
    const float4 a = ((const float4*)g_Op)[idx];
    const float4 b = ((const float4*)g_Op)[idx + (ROWS * DK / 4)];
    float4 r;
    r.x = (a.x + b.x) * inv;
    r.y = (a.y + b.y) * inv;
    r.z = (a.z + b.z) * inv;
    r.w = (a.w + b.w) * inv;
    ((float4*)out)[idx] = r;
}

// ---------------------------------------------------------------------------
extern "C" void kernel_launch(void* const* d_in, const int* in_sizes, int n_in,
                              void* d_out, int out_size)
{
    const float* X  = (const float*)d_in[0];
    // d_in[1] cultural_embedding, d_in[8..10] WC,bC,lam: softmax-invariant -> unused
    const float* WQ = (const float*)d_in[2];
    const float* bQ = (const float*)d_in[3];
    const float* WK = (const float*)d_in[4];
    const float* bK = (const float*)d_in[5];
    const float* WV = (const float*)d_in[6];
    const float* bV = (const float*)d_in[7];
    float* out = (float*)d_out;

    cudaFuncSetAttribute(proj_tc,   cudaFuncAttributeMaxDynamicSharedMemorySize, P_TOTAL);
    cudaFuncSetAttribute(flash_mma, cudaFuncAttributeMaxDynamicSharedMemorySize, SM_TOTAL);

    prep_all<<<256 + XCONV_BLKS, 256>>>(X, WQ, bQ, WK, bK, WV, bV);
    proj_tc<<<dim3(ROWS / 256, 2), 128, P_TOTAL>>>();
    flash_mma<<<dim3(SEQ / BM, BATCH, NZ), 128, SM_TOTAL>>>();
    combine<<<ROWS * DK / 4 / 256, 256>>>(out);
}

// round 15
// speedup vs baseline: 1.6207x; 1.2232x over previous
#include <cuda_runtime.h>
#include <cuda_fp16.h>
#include <cstdint>

#define BATCH 4
#define SEQ   4096
#define DM    1024
#define DK    64
#define ROWS  (BATCH*SEQ)
#define NOUT  192           // Q|K|V concat

#define BM 128              // queries per CTA (flash)
#define BN 64               // kv per tile
#define NT (SEQ/BN)         // 64 tiles total
#define NZ 2                // KV splits
#define NTZ (NT/NZ)         // 32 tiles per split

// ---------------------------------------------------------------------------
// Global scratch (fp16 operands; fp32 partials for split-KV combine).
// ---------------------------------------------------------------------------
__device__ __half g_Qf [ROWS*DK];
__device__ __half g_Kf [ROWS*DK];
__device__ __half g_Vt [DK*ROWS];      // transposed [d][row]
__device__ __half g_WT [NOUT*DM];      // W^T [n][k], fp16
__device__ float  g_bias[NOUT];
__device__ float  g_Op[NZ*ROWS*DK];    // unnormalized O partials
__device__ float  g_lp[NZ*ROWS];       // row-sum partials

// ---------------------------------------------------------------------------
// Helpers (base-target PTX only)
// ---------------------------------------------------------------------------
__device__ __forceinline__ uint32_t smem_to_u32(const void* p) {
    uint32_t a;
    asm("{ .reg .u64 t; cvta.to.shared.u64 t, %1; cvt.u32.u64 %0, t; }" : "=r"(a) : "l"(p));
    return a;
}
__device__ __forceinline__ void cpasync16(uint32_t dst, const void* src) {
    asm volatile("cp.async.cg.shared.global [%0], [%1], 16;" :: "r"(dst), "l"(src));
}
#define CP_COMMIT() asm volatile("cp.async.commit_group;" ::: "memory")
#define CP_WAIT0()  asm volatile("cp.async.wait_group 0;" ::: "memory")
#define CP_WAIT1()  asm volatile("cp.async.wait_group 1;" ::: "memory")

__device__ __forceinline__ void ldsm_x4(uint32_t* r, uint32_t a) {
    asm volatile("ldmatrix.sync.aligned.m8n8.x4.shared.b16 {%0,%1,%2,%3}, [%4];"
        : "=r"(r[0]), "=r"(r[1]), "=r"(r[2]), "=r"(r[3]) : "r"(a));
}
__device__ __forceinline__ void mma_f16(float* d, const uint32_t* a,
                                        uint32_t b0, uint32_t b1) {
    asm volatile("mma.sync.aligned.m16n8k16.row.col.f32.f16.f16.f32 "
        "{%0,%1,%2,%3}, {%4,%5,%6,%7}, {%8,%9}, {%0,%1,%2,%3};"
        : "+f"(d[0]), "+f"(d[1]), "+f"(d[2]), "+f"(d[3])
        : "r"(a[0]), "r"(a[1]), "r"(a[2]), "r"(a[3]), "r"(b0), "r"(b1));
}
__device__ __forceinline__ uint32_t pack_h2(float x, float y) {
    __half2 t = __floats2half2_rn(x, y);
    return *reinterpret_cast<uint32_t*>(&t);
}
__device__ __forceinline__ uint32_t ex2_h2(uint32_t s) {
    uint32_t d;
    asm("ex2.approx.f16x2 %0, %1;" : "=r"(d) : "r"(s));
    return d;
}
__device__ __forceinline__ __half2 u2h2(uint32_t v) {
    return *reinterpret_cast<__half2*>(&v);
}

#define RSTRIDE 144u        // padded 16-bit row stride in bytes (72 elems)

// ---------------------------------------------------------------------------
// Prep: W^T fp16 (QSC folded into Q cols) + bias. 256 blocks x 4 k-cols.
// ---------------------------------------------------------------------------
__global__ __launch_bounds__(256) void prep_w(
    const float* __restrict__ WQ, const float* __restrict__ bQ,
    const float* __restrict__ WK, const float* __restrict__ bK,
    const float* __restrict__ WV, const float* __restrict__ bV)
{
    __shared__ float s[NOUT][5];
    const float QSC = 0.125f * 1.4426950408889634f;
    const int tid = threadIdx.x;
    const int k0 = blockIdx.x * 4;

    #pragma unroll
    for (int i = 0; i < 3; i++) {
        int idx = tid + i * 256;
        int k = idx / NOUT, n = idx - k * NOUT;
        float w;
        if (n < 64)       w = WQ[(size_t)(k0 + k) * DK + n] * QSC;
        else if (n < 128) w = WK[(size_t)(k0 + k) * DK + (n - 64)];
        else              w = WV[(size_t)(k0 + k) * DK + (n - 128)];
        s[n][k] = w;
    }
    __syncthreads();
    if (tid < NOUT) {
        __half hv[4];
        #pragma unroll
        for (int k = 0; k < 4; k++) hv[k] = __float2half_rn(s[tid][k]);
        *(uint2*)(g_WT + (size_t)tid * DM + k0) = *(uint2*)hv;
    }
    if (blockIdx.x == 0 && tid < NOUT) {
        float bb;
        if (tid < 64)       bb = bQ[tid] * QSC;
        else if (tid < 128) bb = bK[tid - 64];
        else                bb = bV[tid - 128];
        g_bias[tid] = bb;
    }
}

// ---------------------------------------------------------------------------
// Tensorized projection: grid (rows/128, 2), 128 threads (4 warps x 32 rows).
// X read directly as fp32 (coalesced LDG.128, convert in regs, STS fp16).
// W fp16 via cp.async. 63KB smem, 2 CTAs/SM.
// ---------------------------------------------------------------------------
#define P_XB    0u            // X bufs: buf*18432 (128 rows, fp16)
#define P_WB    36864u        // W bufs: buf*13824 (96 rows)
#define P_BIAS  64512u        // 96 floats
#define P_TOTAL 64896u

__global__ __launch_bounds__(128, 2) void proj_tc(const float* __restrict__ X)
{
    extern __shared__ char smem[];
    const uint32_t sb = smem_to_u32(smem);
    const int tid  = threadIdx.x;
    const int wid  = tid >> 5;
    const int lane = tid & 31;
    const int gid  = lane >> 2;
    const int tq   = lane & 3;
    const int r0g  = blockIdx.x * 128;
    const int nbase = blockIdx.y * 96;

    float* biass = (float*)(smem + P_BIAS);
    if (tid < 96) biass[tid] = g_bias[nbase + tid];

    // X load mapping: idx = tid + t*128, t<16 ; row = idx>>4, c = idx&15
    // (coalesced: each warp covers 2 rows x 256B)
    const int xrow = tid >> 4;            // base row for t-steps: row = xrow + t*8
    const int xc   = tid & 15;            // float4 index within 64-k chunk

    // ---- prologue: W chunk0 (cp.async) + X chunk0 (LDG+convert+STS)
    {
        #pragma unroll
        for (int t = 0; t < 6; t++) {
            int idx = tid + t * 128;
            int row = idx >> 3, c = idx & 7;
            cpasync16(sb + P_WB + (uint32_t)row * RSTRIDE + c * 16,
                      g_WT + (size_t)(nbase + row) * DM + c * 8);
        }
        CP_COMMIT();
        float4 xr[16];
        #pragma unroll
        for (int t = 0; t < 16; t++) {
            int row = xrow + t * 8;
            xr[t] = *(const float4*)(X + (size_t)(r0g + row) * DM + xc * 4);
        }
        #pragma unroll
        for (int t = 0; t < 16; t++) {
            int row = xrow + t * 8;
            uint2 v;
            v.x = pack_h2(xr[t].x, xr[t].y);
            v.y = pack_h2(xr[t].z, xr[t].w);
            *(uint2*)(smem + P_XB + (uint32_t)row * RSTRIDE + xc * 8) = v;
        }
        CP_WAIT0();
        __syncthreads();
    }

    float O[2][12][4];
    #pragma unroll
    for (int m = 0; m < 2; m++)
        #pragma unroll
        for (int n = 0; n < 12; n++)
            #pragma unroll
            for (int c = 0; c < 4; c++) O[m][n][c] = 0.f;

    const uint32_t aoff0 = (uint32_t)(wid * 32 + (lane & 15)) * RSTRIDE + (uint32_t)(lane >> 4) * 16;
    const uint32_t aoff1 = aoff0 + 16 * RSTRIDE;
    const uint32_t boff = (uint32_t)(((lane >> 4) & 1) * 8 + (lane & 7)) * RSTRIDE
                        + (uint32_t)((lane >> 3) & 1) * 16;

    for (int ch = 0; ch < 16; ch++) {
        const uint32_t XB = sb + P_XB + (uint32_t)(ch & 1) * 18432u;
        const uint32_t WB = sb + P_WB + (uint32_t)(ch & 1) * 13824u;
        const int nxt = ch + 1;
        float4 xr[16];

        if (nxt < 16) {
            const uint32_t WB1 = sb + P_WB + (uint32_t)(nxt & 1) * 13824u;
            #pragma unroll
            for (int t = 0; t < 6; t++) {
                int idx = tid + t * 128;
                int row = idx >> 3, c = idx & 7;
                cpasync16(WB1 + (uint32_t)row * RSTRIDE + c * 16,
                          g_WT + (size_t)(nbase + row) * DM + nxt * 64 + c * 8);
            }
            CP_COMMIT();
            #pragma unroll
            for (int t = 0; t < 16; t++) {
                int row = xrow + t * 8;
                xr[t] = *(const float4*)(X + (size_t)(r0g + row) * DM + nxt * 64 + xc * 4);
            }
        }

        // ---- MMA on chunk ch (LDGs for nxt in flight)
        #pragma unroll
        for (int kc = 0; kc < 4; kc++) {
            uint32_t a0[4], a1[4];
            ldsm_x4(a0, XB + aoff0 + kc * 32);
            ldsm_x4(a1, XB + aoff1 + kc * 32);
            #pragma unroll
            for (int p = 0; p < 6; p++) {
                uint32_t wh[4];
                ldsm_x4(wh, WB + boff + (uint32_t)p * (16 * RSTRIDE) + kc * 32);
                mma_f16(O[0][2*p],   a0, wh[0], wh[1]);
                mma_f16(O[0][2*p+1], a0, wh[2], wh[3]);
                mma_f16(O[1][2*p],   a1, wh[0], wh[1]);
                mma_f16(O[1][2*p+1], a1, wh[2], wh[3]);
            }
        }

        if (nxt < 16) {
            const uint32_t xo = P_XB + (uint32_t)(nxt & 1) * 18432u;
            #pragma unroll
            for (int t = 0; t < 16; t++) {
                int row = xrow + t * 8;
                uint2 v;
                v.x = pack_h2(xr[t].x, xr[t].y);
                v.y = pack_h2(xr[t].z, xr[t].w);
                *(uint2*)(smem + xo + (uint32_t)row * RSTRIDE + xc * 8) = v;
            }
            CP_WAIT0();
        }
        __syncthreads();
    }

    // ---- epilogue: +bias, emit fp16 flash operands
    #pragma unroll
    for (int m = 0; m < 2; m++) {
        const int rr0 = r0g + wid * 32 + m * 16 + gid;
        const int rr1 = rr0 + 8;
        #pragma unroll
        for (int nt = 0; nt < 12; nt++) {
            const int cl = nt * 8 + 2 * tq;
            const int cg = nbase + cl;
            const float b0 = biass[cl], b1 = biass[cl + 1];
            float v00 = O[m][nt][0] + b0, v01 = O[m][nt][1] + b1;
            float v10 = O[m][nt][2] + b0, v11 = O[m][nt][3] + b1;
            if (cg < 64) {
                *(__half2*)(g_Qf + (size_t)rr0 * DK + cg) = __floats2half2_rn(v00, v01);
                *(__half2*)(g_Qf + (size_t)rr1 * DK + cg) = __floats2half2_rn(v10, v11);
            } else if (cg < 128) {
                const int ck = cg - 64;
                *(__half2*)(g_Kf + (size_t)rr0 * DK + ck) = __floats2half2_rn(v00, v01);
                *(__half2*)(g_Kf + (size_t)rr1 * DK + ck) = __floats2half2_rn(v10, v11);
            } else {
                const int d0 = cg - 128, d1 = d0 + 1;
                g_Vt[(size_t)d0 * ROWS + rr0] = __float2half_rn(v00);
                g_Vt[(size_t)d1 * ROWS + rr0] = __float2half_rn(v01);
                g_Vt[(size_t)d0 * ROWS + rr1] = __float2half_rn(v10);
                g_Vt[(size_t)d1 * ROWS + rr1] = __float2half_rn(v11);
            }
        }
    }
}

// ---------------------------------------------------------------------------
// Flash attention (verified round-11 body, unchanged): 128 threads
// (4 warps x 32 rows), BM=128, split-KV NZ=2, fp32 S, fp16x2 exp.
// ---------------------------------------------------------------------------
#define SM_QF   0u
#define SM_BUF0 18432u
#define SM_BUFSZ 18432u      // K +0 (9216), V +9216
#define SM_TOTAL (SM_BUF0 + 3*SM_BUFSZ)

__device__ __forceinline__ void load_kv(uint32_t dst, int tid, size_t bSE, int j0)
{
    #pragma unroll
    for (int t = 0; t < 4; t++) {
        int i = tid + t * 128;            // K: 64 rows x 8 chunks
        int row = i >> 3, c = i & 7;
        cpasync16(dst + row * RSTRIDE + c * 16,
                  g_Kf + (bSE + j0 + row) * DK + c * 8);
    }
    #pragma unroll
    for (int t = 0; t < 4; t++) {
        int i = tid + t * 128;            // V: [d][key]
        int d = i >> 3, c = i & 7;
        cpasync16(dst + 9216u + d * RSTRIDE + c * 16,
                  g_Vt + (size_t)d * ROWS + bSE + j0 + c * 8);
    }
}

__global__ __launch_bounds__(128, 2) void flash_mma()
{
    extern __shared__ char smem[];
    const uint32_t sb = smem_to_u32(smem);
    const int tid  = threadIdx.x;
    const int wid  = tid >> 5;
    const int lane = tid & 31;
    const int gid  = lane >> 2;
    const int tq   = lane & 3;

    const int b  = blockIdx.y;
    const int q0 = blockIdx.x * BM;
    const int z  = blockIdx.z;
    const int k0base = z * NTZ * BN;
    const size_t bSE = (size_t)b * SEQ;

    #pragma unroll
    for (int t = 0; t < 8; t++) {
        int idx = tid + t * 128;          // 128 rows x 8 chunks
        int row = idx >> 3, c = idx & 7;
        cpasync16(sb + SM_QF + row * RSTRIDE + c * 16,
                  g_Qf + (bSE + q0 + row) * DK + c * 8);
    }
    load_kv(sb + SM_BUF0, tid, bSE, k0base);
    CP_COMMIT();
    load_kv(sb + SM_BUF0 + SM_BUFSZ, tid, bSE, k0base + BN);
    CP_COMMIT();
    CP_WAIT1();
    __syncthreads();

    uint32_t qf[2][4][4];
    {
        const uint32_t a0 = (uint32_t)(wid * 32 + (lane & 15)) * RSTRIDE + (uint32_t)(lane >> 4) * 16;
        #pragma unroll
        for (int kc = 0; kc < 4; kc++) {
            ldsm_x4(qf[0][kc], sb + SM_QF + a0 + kc * 32);
            ldsm_x4(qf[1][kc], sb + SM_QF + a0 + 16 * RSTRIDE + kc * 32);
        }
    }

    float O[2][8][4];
    #pragma unroll
    for (int m = 0; m < 2; m++)
        #pragma unroll
        for (int i = 0; i < 8; i++)
            #pragma unroll
            for (int c = 0; c < 4; c++) O[m][i][c] = 0.f;
    float lsum[2][2] = {{0.f, 0.f}, {0.f, 0.f}};

    const uint32_t boff = (uint32_t)(((lane >> 4) & 1) * 8 + (lane & 7)) * RSTRIDE
                        + (uint32_t)((lane >> 3) & 1) * 16;

    const uint32_t bufs[3] = {sb + SM_BUF0, sb + SM_BUF0 + SM_BUFSZ, sb + SM_BUF0 + 2*SM_BUFSZ};

    for (int j = 0; j < NTZ; j++) {
        const uint32_t buf = bufs[j % 3];

        float S[2][8][4];
        #pragma unroll
        for (int m = 0; m < 2; m++)
            #pragma unroll
            for (int i = 0; i < 8; i++)
                #pragma unroll
                for (int c = 0; c < 4; c++) S[m][i][c] = 0.f;

        #pragma unroll
        for (int kc = 0; kc < 4; kc++) {
            #pragma unroll
            for (int nph = 0; nph < 2; nph++) {
                uint32_t r0[4], r1[4];
                ldsm_x4(r0, buf + boff + (uint32_t)(2*nph)   * (16 * RSTRIDE) + kc * 32);
                ldsm_x4(r1, buf + boff + (uint32_t)(2*nph+1) * (16 * RSTRIDE) + kc * 32);
                #pragma unroll
                for (int m = 0; m < 2; m++) {
                    mma_f16(S[m][4*nph],   qf[m][kc], r0[0], r0[1]);
                    mma_f16(S[m][4*nph+1], qf[m][kc], r0[2], r0[3]);
                    mma_f16(S[m][4*nph+2], qf[m][kc], r1[0], r1[1]);
                    mma_f16(S[m][4*nph+3], qf[m][kc], r1[2], r1[3]);
                }
            }
        }

        uint32_t Pf[2][4][4];
        #pragma unroll
        for (int m = 0; m < 2; m++) {
            __half2 a0 = __floats2half2_rn(0.f, 0.f);
            __half2 a1 = a0;
            #pragma unroll
            for (int kc2 = 0; kc2 < 4; kc2++) {
                const int nt0 = 2 * kc2, nt1 = nt0 + 1;
                Pf[m][kc2][0] = ex2_h2(pack_h2(S[m][nt0][0], S[m][nt0][1]));
                Pf[m][kc2][1] = ex2_h2(pack_h2(S[m][nt0][2], S[m][nt0][3]));
                Pf[m][kc2][2] = ex2_h2(pack_h2(S[m][nt1][0], S[m][nt1][1]));
                Pf[m][kc2][3] = ex2_h2(pack_h2(S[m][nt1][2], S[m][nt1][3]));
                a0 = __hadd2(a0, __hadd2(u2h2(Pf[m][kc2][0]), u2h2(Pf[m][kc2][2])));
                a1 = __hadd2(a1, __hadd2(u2h2(Pf[m][kc2][1]), u2h2(Pf[m][kc2][3])));
            }
            lsum[m][0] += __low2float(a0) + __high2float(a0);
            lsum[m][1] += __low2float(a1) + __high2float(a1);
        }

        #pragma unroll
        for (int kc2 = 0; kc2 < 4; kc2++) {
            #pragma unroll
            for (int nph = 0; nph < 2; nph++) {
                uint32_t r0[4], r1[4];
                ldsm_x4(r0, buf + 9216u + boff + (uint32_t)(2*nph)   * (16 * RSTRIDE) + kc2 * 32);
                ldsm_x4(r1, buf + 9216u + boff + (uint32_t)(2*nph+1) * (16 * RSTRIDE) + kc2 * 32);
                #pragma unroll
                for (int m = 0; m < 2; m++) {
                    mma_f16(O[m][4*nph],   Pf[m][kc2], r0[0], r0[1]);
                    mma_f16(O[m][4*nph+1], Pf[m][kc2], r0[2], r0[3]);
                    mma_f16(O[m][4*nph+2], Pf[m][kc2], r1[0], r1[1]);
                    mma_f16(O[m][4*nph+3], Pf[m][kc2], r1[2], r1[3]);
                }
            }
        }

        if (j + 2 < NTZ) {
            load_kv(bufs[(j + 2) % 3], tid, bSE, k0base + (j + 2) * BN);
            CP_COMMIT();
            CP_WAIT1();
        } else {
            CP_WAIT0();
        }
        __syncthreads();
    }

    #pragma unroll
    for (int m = 0; m < 2; m++) {
        lsum[m][0] += __shfl_xor_sync(0xffffffffu, lsum[m][0], 1);
        lsum[m][0] += __shfl_xor_sync(0xffffffffu, lsum[m][0], 2);
        lsum[m][1] += __shfl_xor_sync(0xffffffffu, lsum[m][1], 1);
        lsum[m][1] += __shfl_xor_sync(0xffffffffu, lsum[m][1], 2);

        const int row0 = q0 + wid * 32 + m * 16 + gid;
        float* o0 = g_Op + ((size_t)z * ROWS + bSE + row0) * DK;
        float* o1 = o0 + 8 * DK;
        if (tq == 0) {
            g_lp[(size_t)z * ROWS + bSE + row0]     = lsum[m][0];
            g_lp[(size_t)z * ROWS + bSE + row0 + 8] = lsum[m][1];
        }
        #pragma unroll
        for (int nt = 0; nt < 8; nt++) {
            const int col = nt * 8 + 2 * tq;
            *(float2*)(o0 + col) = make_float2(O[m][nt][0], O[m][nt][1]);
            *(float2*)(o1 + col) = make_float2(O[m][nt][2], O[m][nt][3]);
        }
    }
}

// ---------------------------------------------------------------------------
// Combine: out = (O0 + O1) / (l0 + l1)
// ---------------------------------------------------------------------------
__global__ __launch_bounds__(256) void combine(float* __restrict__ out)
{
    const int idx = blockIdx.x * 256 + threadIdx.x;   // float4 index, 16/row
    const int row = idx >> 4;
    const float inv = 1.f / (g_lp[row] + g_lp[ROWS + row]);
    const float4 a = ((const float4*)g_Op)[idx];
    const float4 b = ((const float4*)g_Op)[idx + (ROWS * DK / 4)];
    float4 r;
    r.x = (a.x + b.x) * inv;
    r.y = (a.y + b.y) * inv;
    r.z = (a.z + b.z) * inv;
    r.w = (a.w + b.w) * inv;
    ((float4*)out)[idx] = r;
}

// ---------------------------------------------------------------------------
extern "C" void kernel_launch(void* const* d_in, const int* in_sizes, int n_in,
                              void* d_out, int out_size)
{
    const float* X  = (const float*)d_in[0];
    // d_in[1] cultural_embedding, d_in[8..10] WC,bC,lam: softmax-invariant -> unused
    const float* WQ = (const float*)d_in[2];
    const float* bQ = (const float*)d_in[3];
    const float* WK = (const float*)d_in[4];
    const float* bK = (const float*)d_in[5];
    const float* WV = (const float*)d_in[6];
    const float* bV = (const float*)d_in[7];
    float* out = (float*)d_out;

    cudaFuncSetAttribute(proj_tc,   cudaFuncAttributeMaxDynamicSharedMemorySize, P_TOTAL);
    cudaFuncSetAttribute(flash_mma, cudaFuncAttributeMaxDynamicSharedMemorySize, SM_TOTAL);

    prep_w<<<DM / 4, 256>>>(WQ, bQ, WK, bK, WV, bV);
    proj_tc<<<dim3(ROWS / 128, 2), 128, P_TOTAL>>>(X);
    flash_mma<<<dim3(SEQ / BM, BATCH, NZ), 128, SM_TOTAL>>>();
    combine<<<ROWS * DK / 4 / 256, 256>>>(out);
}